// round 15
// baseline (speedup 1.0000x reference)
#include <cuda_runtime.h>

// Problem constants (from reference setup_inputs)
#define Bc    4
#define Nc    16384
#define Kc    27
#define BNc   (Bc * Nc)            // 65536
#define Tc    (BNc * Kc)           // 1769472
#define BASEc 70
#define BASE3 343000               // 70^3
#define TABLE_SIZE (Bc * BASE3)    // 1372000
#define SHIFTc 3

#define NWORDS (Tc / 32)           // 55296 bitmask words (exact)
#define S1_BLOCKS (NWORDS / 256)   // 216 (exact)

// Scratch (__device__ globals; addresses formed only in device code — r7 lesson).
// 64-bit epoch-tagged table: value = (epoch<<32)|(Tc-1-t); atomicMax == min-t.
// Stale epochs lose automatically => no per-call table init. Epoch bumped in
// k_out (stream-ordered after the last table reader, k_bitset).
__device__ __align__(16) unsigned long long g_table[TABLE_SIZE];
__device__ int g_oi[TABLE_SIZE];                      // dense rank per key
__device__ int g_keybase[BNc];                        // encoded center key per point
__device__ __align__(16) unsigned g_bits[NWORDS];     // bit t set <=> first occurrence
__device__ int g_bsum2[S1_BLOCKS];                    // per-scan-block popc totals
__device__ int g_bpre2[S1_BLOCKS];                    // exclusive prefix of block totals
__device__ int g_numout;                              // unique key count
__device__ unsigned g_epoch = 1;                      // call epoch (bumped in k_out)
__device__ int g_cnt = 0;                             // scan completion counter (self-resetting)
__device__ volatile unsigned g_done = 0;              // top-scan-done flag (== epoch)

// key delta per kernel offset k ('ij' meshgrid order)
__constant__ int c_delta[Kc] = {
    -4971, -4970, -4969,  -4901, -4900, -4899,  -4831, -4830, -4829,
      -71,   -70,   -69,     -1,     0,     1,     69,    70,    71,
     4829,  4830,  4831,   4899,  4900,  4901,   4969,  4970,  4971
};

// zero any harness padding past 6T+1 (launched only when present)
__global__ void k_tail(float* __restrict__ p, long long n) {
    long long i = (long long)blockIdx.x * blockDim.x + threadIdx.x;
    long long stride = (long long)gridDim.x * blockDim.x;
    for (; i < n; i += stride) p[i] = 0.0f;
}

// One thread per (point, offset): epoch-tagged atomicMax; zero bits inline
// (bits consumed only by the NEXT launch — ordered by the launch boundary).
__global__ void k_build(const int* __restrict__ coords,
                        const int* __restrict__ batch) {
    int t = blockIdx.x * blockDim.x + threadIdx.x;
    if (t >= Tc) return;
    if (t < NWORDS) g_bits[t] = 0u;
    unsigned ep = g_epoch;
    int idx = t / Kc;
    int k   = t - idx * Kc;
    int x = coords[idx * 3 + 0];
    int y = coords[idx * 3 + 1];
    int z = coords[idx * 3 + 2];
    int b = batch[idx];
    int kb = b * BASE3 + ((x + SHIFTc) * BASEc + (y + SHIFTc)) * BASEc + (z + SHIFTc);
    if (k == 0) g_keybase[idx] = kb;
    unsigned long long v = ((unsigned long long)ep << 32) | (unsigned)(Tc - 1 - t);
    atomicMax(&g_table[kb + c_delta[k]], v);
}

// Table pass (last table reader): occupied key -> set bit at its min-t.
__global__ void k_bitset() {
    int i = blockIdx.x * blockDim.x + threadIdx.x;
    if (i >= TABLE_SIZE / 4) return;
    unsigned ep = g_epoch;
    ulonglong2 v0 = ((const ulonglong2*)g_table)[2 * i];
    ulonglong2 v1 = ((const ulonglong2*)g_table)[2 * i + 1];
#pragma unroll
    for (int j = 0; j < 4; j++) {
        unsigned long long v = (j < 2) ? ((j == 0) ? v0.x : v0.y)
                                       : ((j == 2) ? v1.x : v1.y);
        if ((unsigned)(v >> 32) == ep) {
            int ft = Tc - 1 - (int)(unsigned)v;
            atomicOr(&g_bits[ft >> 5], 1u << (ft & 31));
        }
    }
}

// Fused scan + emit. 216 blocks x 256 threads, one bitmask word per thread.
//  1) block scan of popcounts -> local exclusive prefix (registers)
//  2) last-done block scans the 216 block totals (r12-proven), sets g_done=ep
//  3) all blocks: rank = bpre2[blk] + local prefix; iterate set bits in
//     t-order -> ranks SEQUENTIAL -> dense out_key stores, g_oi scatter.
__global__ void k_scan_emit(float* __restrict__ out) {
    __shared__ int wsum[8];
    __shared__ int sh[256];
    __shared__ int sh_pos;
    const int tid = threadIdx.x;
    const int lane = tid & 31, wid = tid >> 5;
    const unsigned ep = g_epoch;
    const int w = blockIdx.x * 256 + tid;

    const unsigned bits = g_bits[w];
    const int c = __popc(bits);
    int incl = c;
#pragma unroll
    for (int d = 1; d < 32; d <<= 1) {
        int v = __shfl_up_sync(0xffffffffu, incl, d);
        if (lane >= d) incl += v;
    }
    if (lane == 31) wsum[wid] = incl;
    __syncthreads();
    if (wid == 0) {
        int v = (lane < 8) ? wsum[lane] : 0;
#pragma unroll
        for (int d = 1; d < 8; d <<= 1) {
            int u = __shfl_up_sync(0xffffffffu, v, d);
            if (lane >= d) v += u;
        }
        if (lane < 8) wsum[lane] = v;
    }
    __syncthreads();
    const int pre = ((wid == 0) ? 0 : wsum[wid - 1]) + incl - c;  // local exclusive
    if (tid == 255) g_bsum2[blockIdx.x] = wsum[7];

    __threadfence();
    __syncthreads();
    if (tid == 0) sh_pos = atomicAdd(&g_cnt, 1);
    __syncthreads();
    if (sh_pos == S1_BLOCKS - 1) {                   // last-done block: top scan
        if (tid == 0) g_cnt = 0;                     // rearm for next call
        int v = (tid < S1_BLOCKS) ? g_bsum2[tid] : 0;
        sh[tid] = v;
        __syncthreads();
#pragma unroll
        for (int d = 1; d < 256; d <<= 1) {
            int u = (tid >= d) ? sh[tid - d] : 0;
            __syncthreads();
            sh[tid] += u;
            __syncthreads();
        }
        if (tid < S1_BLOCKS) g_bpre2[tid] = sh[tid] - v;
        if (tid == S1_BLOCKS - 1) {
            g_numout = sh[tid];
            out[6LL * Tc] = (float)sh[tid];          // num_out
        }
        __threadfence();
        __syncthreads();
        if (tid == 0) g_done = ep;                   // release waiters
    } else {                                         // other blocks: spin on flag
        if (tid == 0) { while (g_done != ep) __nanosleep(64); }
        __syncthreads();
    }

    // ---- emit in t-order: sequential ranks ----
    if (!bits) return;
    int rank = g_bpre2[blockIdx.x] + pre;
    unsigned m = bits;
    while (m) {
        int bit = __ffs(m) - 1;
        m &= m - 1;
        int ft  = w * 32 + bit;
        int idx = ft / Kc;
        int k   = ft - idx * Kc;
        int key = g_keybase[idx] + c_delta[k];
        g_oi[key] = rank;                            // random scatter (unavoidable)
        int rem = key % BASE3;
        int xx = rem / (BASEc * BASEc) - SHIFTc;
        int yy = (rem / BASEc) % BASEc - SHIFTc;
        int zz = rem % BASEc - SHIFTc;
        float* p = out + 3LL * Tc + 3LL * rank;      // DENSE sequential store
        p[0] = (float)xx; p[1] = (float)yy; p[2] = (float)zz;
        rank++;
    }
}

// Final: 8 t's per thread: in_idx/out_idx/rel_pos (float4 x2 per stream) +
// out_key -1 padding. Bumps epoch for the next call (stream-ordered after the
// last g_epoch/table consumers).
__global__ void k_out(float* __restrict__ out) {
    int i = blockIdx.x * blockDim.x + threadIdx.x;
    if (i == 0) g_epoch++;                           // one thread
    if (i >= Tc / 8) return;
    int no = g_numout;
    int t0 = i * 8;
    float va[8], vb[8], vc[8];
#pragma unroll
    for (int j = 0; j < 8; j++) {
        int t   = t0 + j;
        int idx = t / Kc;
        int k   = t - idx * Kc;
        int key = g_keybase[idx] + c_delta[k];
        va[j] = (float)(idx & (Nc - 1));
        vb[j] = (float)g_oi[key];
        vc[j] = (float)k;
    }
    float4* pa = (float4*)out;
    float4* pb = (float4*)(out + 1LL * Tc);
    float4* pc = (float4*)(out + 2LL * Tc);
    pa[2 * i]     = make_float4(va[0], va[1], va[2], va[3]);
    pa[2 * i + 1] = make_float4(va[4], va[5], va[6], va[7]);
    pb[2 * i]     = make_float4(vb[0], vb[1], vb[2], vb[3]);
    pb[2 * i + 1] = make_float4(vb[4], vb[5], vb[6], vb[7]);
    pc[2 * i]     = make_float4(vc[0], vc[1], vc[2], vc[3]);
    pc[2 * i + 1] = make_float4(vc[4], vc[5], vc[6], vc[7]);

    if (t0 >= no) {                                  // fully padded: 6x float4
        float4 m1 = make_float4(-1.f, -1.f, -1.f, -1.f);
        float4* p = (float4*)(out + 3LL * Tc + 24LL * i);
#pragma unroll
        for (int j = 0; j < 6; j++) p[j] = m1;
    } else if (t0 + 7 >= no) {                       // boundary: scalar
#pragma unroll
        for (int j = 0; j < 8; j++) {
            int t = t0 + j;
            if (t >= no) {
                float* p = out + 3LL * Tc + 3LL * t;
                p[0] = -1.f; p[1] = -1.f; p[2] = -1.f;
            }
        }
    }
}

extern "C" void kernel_launch(void* const* d_in, const int* in_sizes, int n_in,
                              void* d_out, int out_size) {
    // Identify inputs by SIZE: coordinates = [B,N,3] (3*BNc), batch = [B,N] (BNc).
    const int* coords = (const int*)d_in[0];
    const int* batch  = (const int*)d_in[n_in > 1 ? 1 : 0];
    for (int i = 0; i < n_in; i++) {
        if (in_sizes[i] == 3 * BNc) coords = (const int*)d_in[i];
        else if (in_sizes[i] == BNc) batch = (const int*)d_in[i];
    }
    float* out = (float*)d_out;
    long long osz = (long long)out_size;

    long long tail = osz - (6LL * Tc + 1);
    if (tail > 0) k_tail<<<512, 256>>>(out + 6LL * Tc + 1, tail);

    k_build<<<(Tc + 255) / 256, 256>>>(coords, batch);
    k_bitset<<<(TABLE_SIZE / 4 + 255) / 256, 256>>>();
    k_scan_emit<<<S1_BLOCKS, 256>>>(out);
    k_out<<<(Tc / 8 + 255) / 256, 256>>>(out);
}

// round 16
// speedup vs baseline: 1.3811x; 1.3811x over previous
#include <cuda_runtime.h>

// Problem constants (from reference setup_inputs)
#define Bc    4
#define Nc    16384
#define Kc    27
#define BNc   (Bc * Nc)            // 65536
#define Tc    (BNc * Kc)           // 1769472
#define BASEc 70
#define BASE3 343000               // 70^3
#define TABLE_SIZE (Bc * BASE3)    // 1372000
#define SHIFTc 3

#define NWORDS (Tc / 32)           // 55296 bitmask words (exact)
#define S1_BLOCKS (NWORDS / 256)   // 216 (exact)

// Scratch (__device__ globals; addresses formed only in device code — r7 lesson).
// 64-bit epoch-tagged table: value = (epoch<<32)|(Tc-1-t); atomicMax == min-t.
// Stale epochs lose automatically => no per-call table init. Epoch bumped in
// k_out (stream-ordered after the last table/epoch consumers).
__device__ __align__(16) unsigned long long g_table[TABLE_SIZE];
__device__ int g_oi[TABLE_SIZE];                      // dense rank per key
__device__ int g_keybase[BNc];                        // encoded center key per point
__device__ __align__(16) unsigned g_bits[NWORDS];     // bit t set <=> first occurrence
__device__ int g_wordpre[NWORDS];                     // per-word exclusive popc prefix (within scan block)
__device__ int g_bsum2[S1_BLOCKS];                    // per-scan-block popc totals
__device__ int g_bpre2[S1_BLOCKS];                    // exclusive prefix of block totals
__device__ int g_numout;                              // unique key count
__device__ unsigned g_epoch = 1;                      // call epoch (bumped in k_out)
__device__ int g_cnt = 0;                             // scan completion counter (self-resetting)

// key delta per kernel offset k ('ij' meshgrid order)
__constant__ int c_delta[Kc] = {
    -4971, -4970, -4969,  -4901, -4900, -4899,  -4831, -4830, -4829,
      -71,   -70,   -69,     -1,     0,     1,     69,    70,    71,
     4829,  4830,  4831,   4899,  4900,  4901,   4969,  4970,  4971
};

// zero any harness padding past 6T+1 (launched only when present)
__global__ void k_tail(float* __restrict__ p, long long n) {
    long long i = (long long)blockIdx.x * blockDim.x + threadIdx.x;
    long long stride = (long long)gridDim.x * blockDim.x;
    for (; i < n; i += stride) p[i] = 0.0f;
}

// One thread per (point, offset): epoch-tagged atomicMax; zero bits inline.
__global__ void k_build(const int* __restrict__ coords,
                        const int* __restrict__ batch) {
    int t = blockIdx.x * blockDim.x + threadIdx.x;
    if (t >= Tc) return;
    if (t < NWORDS) g_bits[t] = 0u;
    unsigned ep = g_epoch;
    int idx = t / Kc;
    int k   = t - idx * Kc;
    int x = coords[idx * 3 + 0];
    int y = coords[idx * 3 + 1];
    int z = coords[idx * 3 + 2];
    int b = batch[idx];
    int kb = b * BASE3 + ((x + SHIFTc) * BASEc + (y + SHIFTc)) * BASEc + (z + SHIFTc);
    if (k == 0) g_keybase[idx] = kb;
    unsigned long long v = ((unsigned long long)ep << 32) | (unsigned)(Tc - 1 - t);
    atomicMax(&g_table[kb + c_delta[k]], v);
}

// Table pass: occupied (this epoch) key -> set bit at its min-t.
__global__ void k_bitset() {
    int i = blockIdx.x * blockDim.x + threadIdx.x;
    if (i >= TABLE_SIZE / 4) return;
    unsigned ep = g_epoch;
    ulonglong2 v0 = ((const ulonglong2*)g_table)[2 * i];
    ulonglong2 v1 = ((const ulonglong2*)g_table)[2 * i + 1];
#pragma unroll
    for (int j = 0; j < 4; j++) {
        unsigned long long v = (j < 2) ? ((j == 0) ? v0.x : v0.y)
                                       : ((j == 2) ? v1.x : v1.y);
        if ((unsigned)(v >> 32) == ep) {
            int ft = Tc - 1 - (int)(unsigned)v;
            atomicOr(&g_bits[ft >> 5], 1u << (ft & 31));
        }
    }
}

// Scan: 216 blocks x 256 words; per-word exclusive prefix + fused top scan
// in the last-done block (r12-proven). Writes num_out.
__global__ void k_scan(float* __restrict__ out) {
    __shared__ int wsum[8];
    __shared__ int sh[256];
    __shared__ int sh_pos;
    int tid = threadIdx.x;
    int lane = tid & 31, wid = tid >> 5;
    int w = blockIdx.x * 256 + tid;
    int c = __popc(g_bits[w]);
    int incl = c;
#pragma unroll
    for (int d = 1; d < 32; d <<= 1) {
        int v = __shfl_up_sync(0xffffffffu, incl, d);
        if (lane >= d) incl += v;
    }
    if (lane == 31) wsum[wid] = incl;
    __syncthreads();
    if (wid == 0) {
        int v = (lane < 8) ? wsum[lane] : 0;
#pragma unroll
        for (int d = 1; d < 8; d <<= 1) {
            int u = __shfl_up_sync(0xffffffffu, v, d);
            if (lane >= d) v += u;
        }
        if (lane < 8) wsum[lane] = v;
    }
    __syncthreads();
    g_wordpre[w] = ((wid == 0) ? 0 : wsum[wid - 1]) + incl - c;
    if (tid == 255) g_bsum2[blockIdx.x] = wsum[7];

    __threadfence();
    __syncthreads();
    if (tid == 0) sh_pos = atomicAdd(&g_cnt, 1);
    __syncthreads();
    if (sh_pos == S1_BLOCKS - 1) {
        if (tid == 0) g_cnt = 0;                     // rearm for next call
        int v = (tid < S1_BLOCKS) ? g_bsum2[tid] : 0;
        sh[tid] = v;
        __syncthreads();
#pragma unroll
        for (int d = 1; d < 256; d <<= 1) {
            int u = (tid >= d) ? sh[tid - d] : 0;
            __syncthreads();
            sh[tid] += u;
            __syncthreads();
        }
        if (tid < S1_BLOCKS) g_bpre2[tid] = sh[tid] - v;
        if (tid == S1_BLOCKS - 1) {
            g_numout = sh[tid];
            out[6LL * Tc] = (float)sh[tid];          // num_out
        }
    }
}

// Emit: ONE WARP PER WORD (full Tc-thread parallelism). Broadcast loads of
// bits/wordpre/bpre2; set-bit lanes have CONSECUTIVE ranks -> coalesced
// out_key stores; only the g_oi scatter is random.
__global__ void k_emit(float* __restrict__ out) {
    int gtid = blockIdx.x * blockDim.x + threadIdx.x;
    int w    = gtid >> 5;                            // word index
    int lane = gtid & 31;
    if (w >= NWORDS) return;
    unsigned bits = g_bits[w];                       // warp-broadcast
    if (!(bits >> lane & 1u)) return;
    int rank = g_bpre2[w >> 8] + g_wordpre[w] + __popc(bits & ((1u << lane) - 1u));
    int ft   = w * 32 + lane;
    int idx  = ft / Kc;
    int k    = ft - idx * Kc;
    int key  = g_keybase[idx] + c_delta[k];
    g_oi[key] = rank;                                // random scatter (unavoidable)
    int rem = key % BASE3;
    int xx = rem / (BASEc * BASEc) - SHIFTc;
    int yy = (rem / BASEc) % BASEc - SHIFTc;
    int zz = rem % BASEc - SHIFTc;
    float* p = out + 3LL * Tc + 3LL * rank;          // consecutive ranks -> coalesced
    p[0] = (float)xx; p[1] = (float)yy; p[2] = (float)zz;
}

// Final: 8 t's per thread: in_idx/out_idx/rel_pos (float4 x2 per stream) +
// out_key -1 padding. Bumps epoch for the next call.
__global__ void k_out(float* __restrict__ out) {
    int i = blockIdx.x * blockDim.x + threadIdx.x;
    if (i == 0) g_epoch++;                           // one thread
    if (i >= Tc / 8) return;
    int no = g_numout;
    int t0 = i * 8;
    float va[8], vb[8], vc[8];
#pragma unroll
    for (int j = 0; j < 8; j++) {
        int t   = t0 + j;
        int idx = t / Kc;
        int k   = t - idx * Kc;
        int key = g_keybase[idx] + c_delta[k];
        va[j] = (float)(idx & (Nc - 1));
        vb[j] = (float)g_oi[key];
        vc[j] = (float)k;
    }
    float4* pa = (float4*)out;
    float4* pb = (float4*)(out + 1LL * Tc);
    float4* pc = (float4*)(out + 2LL * Tc);
    pa[2 * i]     = make_float4(va[0], va[1], va[2], va[3]);
    pa[2 * i + 1] = make_float4(va[4], va[5], va[6], va[7]);
    pb[2 * i]     = make_float4(vb[0], vb[1], vb[2], vb[3]);
    pb[2 * i + 1] = make_float4(vb[4], vb[5], vb[6], vb[7]);
    pc[2 * i]     = make_float4(vc[0], vc[1], vc[2], vc[3]);
    pc[2 * i + 1] = make_float4(vc[4], vc[5], vc[6], vc[7]);

    if (t0 >= no) {                                  // fully padded: 6x float4
        float4 m1 = make_float4(-1.f, -1.f, -1.f, -1.f);
        float4* p = (float4*)(out + 3LL * Tc + 24LL * i);
#pragma unroll
        for (int j = 0; j < 6; j++) p[j] = m1;
    } else if (t0 + 7 >= no) {                       // boundary: scalar
#pragma unroll
        for (int j = 0; j < 8; j++) {
            int t = t0 + j;
            if (t >= no) {
                float* p = out + 3LL * Tc + 3LL * t;
                p[0] = -1.f; p[1] = -1.f; p[2] = -1.f;
            }
        }
    }
}

extern "C" void kernel_launch(void* const* d_in, const int* in_sizes, int n_in,
                              void* d_out, int out_size) {
    // Identify inputs by SIZE: coordinates = [B,N,3] (3*BNc), batch = [B,N] (BNc).
    const int* coords = (const int*)d_in[0];
    const int* batch  = (const int*)d_in[n_in > 1 ? 1 : 0];
    for (int i = 0; i < n_in; i++) {
        if (in_sizes[i] == 3 * BNc) coords = (const int*)d_in[i];
        else if (in_sizes[i] == BNc) batch = (const int*)d_in[i];
    }
    float* out = (float*)d_out;
    long long osz = (long long)out_size;

    long long tail = osz - (6LL * Tc + 1);
    if (tail > 0) k_tail<<<512, 256>>>(out + 6LL * Tc + 1, tail);

    k_build<<<(Tc + 255) / 256, 256>>>(coords, batch);
    k_bitset<<<(TABLE_SIZE / 4 + 255) / 256, 256>>>();
    k_scan<<<S1_BLOCKS, 256>>>(out);
    k_emit<<<(Tc + 255) / 256, 256>>>(out);
    k_out<<<(Tc / 8 + 255) / 256, 256>>>(out);
}

// round 17
// speedup vs baseline: 1.3952x; 1.0102x over previous
#include <cuda_runtime.h>

// Problem constants (from reference setup_inputs)
#define Bc    4
#define Nc    16384
#define Kc    27
#define BNc   (Bc * Nc)            // 65536
#define Tc    (BNc * Kc)           // 1769472
#define BASEc 70
#define BASE3 343000               // 70^3
#define TABLE_SIZE (Bc * BASE3)    // 1372000
#define SHIFTc 3

#define NWORDS (Tc / 32)           // 55296 bitmask words (exact)
#define S1_BLOCKS (NWORDS / 256)   // 216 (exact)

// Scratch (__device__ globals; addresses formed only in device code — r7 lesson).
// 32-bit table: value = Tc - t (so atomicMax == min-t), 0 = EMPTY. Table starts
// zeroed (module load); k_emit resets exactly the occupied entries back to 0
// (each occupied key has exactly one first-occurrence bit), so no init pass
// and no epoch tagging are needed across graph replays.
__device__ __align__(16) unsigned g_table[TABLE_SIZE];
__device__ int g_oi[TABLE_SIZE];                      // dense rank per key
__device__ int g_keybase[BNc];                        // encoded center key per point
__device__ __align__(16) unsigned g_bits[NWORDS];     // bit t set <=> first occurrence
__device__ int g_wordpre[NWORDS];                     // per-word excl. popc prefix (within scan block)
__device__ int g_bsum2[S1_BLOCKS];                    // per-scan-block popc totals
__device__ int g_bpre2[S1_BLOCKS];                    // exclusive prefix of block totals
__device__ int g_numout;                              // unique key count
__device__ int g_cnt = 0;                             // scan completion counter (self-resetting)

// key delta per kernel offset k ('ij' meshgrid order)
__constant__ int c_delta[Kc] = {
    -4971, -4970, -4969,  -4901, -4900, -4899,  -4831, -4830, -4829,
      -71,   -70,   -69,     -1,     0,     1,     69,    70,    71,
     4829,  4830,  4831,   4899,  4900,  4901,   4969,  4970,  4971
};

// zero any harness padding past 6T+1 (launched only when present)
__global__ void k_tail(float* __restrict__ p, long long n) {
    long long i = (long long)blockIdx.x * blockDim.x + threadIdx.x;
    long long stride = (long long)gridDim.x * blockDim.x;
    for (; i < n; i += stride) p[i] = 0.0f;
}

// One thread per (point, offset): 32-bit atomicMax(Tc - t); zero bits inline.
__global__ void k_build(const int* __restrict__ coords,
                        const int* __restrict__ batch) {
    int t = blockIdx.x * blockDim.x + threadIdx.x;
    if (t >= Tc) return;
    if (t < NWORDS) g_bits[t] = 0u;
    int idx = t / Kc;
    int k   = t - idx * Kc;
    int x = coords[idx * 3 + 0];
    int y = coords[idx * 3 + 1];
    int z = coords[idx * 3 + 2];
    int b = batch[idx];
    int kb = b * BASE3 + ((x + SHIFTc) * BASEc + (y + SHIFTc)) * BASEc + (z + SHIFTc);
    if (k == 0) g_keybase[idx] = kb;
    atomicMax(&g_table[kb + c_delta[k]], (unsigned)(Tc - t));
}

// Table pass: occupied key (v != 0) -> set bit at its min-t.
__global__ void k_bitset() {
    int i = blockIdx.x * blockDim.x + threadIdx.x;
    if (i >= TABLE_SIZE / 4) return;
    uint4 v = ((const uint4*)g_table)[i];
#pragma unroll
    for (int j = 0; j < 4; j++) {
        unsigned u = (&v.x)[j];
        if (u) {
            int ft = Tc - (int)u;
            atomicOr(&g_bits[ft >> 5], 1u << (ft & 31));
        }
    }
}

// Scan: 216 blocks x 256 words; per-word exclusive prefix + fused top scan
// in the last-done block (r12-proven). Writes num_out.
__global__ void k_scan(float* __restrict__ out) {
    __shared__ int wsum[8];
    __shared__ int sh[256];
    __shared__ int sh_pos;
    int tid = threadIdx.x;
    int lane = tid & 31, wid = tid >> 5;
    int w = blockIdx.x * 256 + tid;
    int c = __popc(g_bits[w]);
    int incl = c;
#pragma unroll
    for (int d = 1; d < 32; d <<= 1) {
        int v = __shfl_up_sync(0xffffffffu, incl, d);
        if (lane >= d) incl += v;
    }
    if (lane == 31) wsum[wid] = incl;
    __syncthreads();
    if (wid == 0) {
        int v = (lane < 8) ? wsum[lane] : 0;
#pragma unroll
        for (int d = 1; d < 8; d <<= 1) {
            int u = __shfl_up_sync(0xffffffffu, v, d);
            if (lane >= d) v += u;
        }
        if (lane < 8) wsum[lane] = v;
    }
    __syncthreads();
    g_wordpre[w] = ((wid == 0) ? 0 : wsum[wid - 1]) + incl - c;
    if (tid == 255) g_bsum2[blockIdx.x] = wsum[7];

    __threadfence();
    __syncthreads();
    if (tid == 0) sh_pos = atomicAdd(&g_cnt, 1);
    __syncthreads();
    if (sh_pos == S1_BLOCKS - 1) {
        if (tid == 0) g_cnt = 0;                     // rearm for next call
        int v = (tid < S1_BLOCKS) ? g_bsum2[tid] : 0;
        sh[tid] = v;
        __syncthreads();
#pragma unroll
        for (int d = 1; d < 256; d <<= 1) {
            int u = (tid >= d) ? sh[tid - d] : 0;
            __syncthreads();
            sh[tid] += u;
            __syncthreads();
        }
        if (tid < S1_BLOCKS) g_bpre2[tid] = sh[tid] - v;
        if (tid == S1_BLOCKS - 1) {
            g_numout = sh[tid];
            out[6LL * Tc] = (float)sh[tid];          // num_out
        }
    }
}

// Emit: one warp per word (r16-proven). Set-bit lanes have CONSECUTIVE ranks
// -> coalesced out_key stores. Also RESETS the occupied table entry to 0,
// leaving the table clean for the next call (replaces epoch tagging).
__global__ void k_emit(float* __restrict__ out) {
    int gtid = blockIdx.x * blockDim.x + threadIdx.x;
    int w    = gtid >> 5;                            // word index
    int lane = gtid & 31;
    if (w >= NWORDS) return;
    unsigned bits = g_bits[w];                       // warp-broadcast
    if (!(bits >> lane & 1u)) return;
    int rank = g_bpre2[w >> 8] + g_wordpre[w] + __popc(bits & ((1u << lane) - 1u));
    int ft   = w * 32 + lane;
    int idx  = ft / Kc;
    int k    = ft - idx * Kc;
    int key  = g_keybase[idx] + c_delta[k];
    g_oi[key]    = rank;                             // random scatter
    g_table[key] = 0u;                               // reset for next call (same line)
    int rem = key % BASE3;
    int xx = rem / (BASEc * BASEc) - SHIFTc;
    int yy = (rem / BASEc) % BASEc - SHIFTc;
    int zz = rem % BASEc - SHIFTc;
    float* p = out + 3LL * Tc + 3LL * rank;          // consecutive ranks -> coalesced
    p[0] = (float)xx; p[1] = (float)yy; p[2] = (float)zz;
}

// Final: 8 t's per thread: in_idx/out_idx/rel_pos (float4 x2 per stream) +
// out_key -1 padding for rows [num_out, Tc).
__global__ void k_out(float* __restrict__ out) {
    int i = blockIdx.x * blockDim.x + threadIdx.x;
    if (i >= Tc / 8) return;
    int no = g_numout;
    int t0 = i * 8;
    float va[8], vb[8], vc[8];
#pragma unroll
    for (int j = 0; j < 8; j++) {
        int t   = t0 + j;
        int idx = t / Kc;
        int k   = t - idx * Kc;
        int key = g_keybase[idx] + c_delta[k];
        va[j] = (float)(idx & (Nc - 1));
        vb[j] = (float)g_oi[key];
        vc[j] = (float)k;
    }
    float4* pa = (float4*)out;
    float4* pb = (float4*)(out + 1LL * Tc);
    float4* pc = (float4*)(out + 2LL * Tc);
    pa[2 * i]     = make_float4(va[0], va[1], va[2], va[3]);
    pa[2 * i + 1] = make_float4(va[4], va[5], va[6], va[7]);
    pb[2 * i]     = make_float4(vb[0], vb[1], vb[2], vb[3]);
    pb[2 * i + 1] = make_float4(vb[4], vb[5], vb[6], vb[7]);
    pc[2 * i]     = make_float4(vc[0], vc[1], vc[2], vc[3]);
    pc[2 * i + 1] = make_float4(vc[4], vc[5], vc[6], vc[7]);

    if (t0 >= no) {                                  // fully padded: 6x float4
        float4 m1 = make_float4(-1.f, -1.f, -1.f, -1.f);
        float4* p = (float4*)(out + 3LL * Tc + 24LL * i);
#pragma unroll
        for (int j = 0; j < 6; j++) p[j] = m1;
    } else if (t0 + 7 >= no) {                       // boundary: scalar
#pragma unroll
        for (int j = 0; j < 8; j++) {
            int t = t0 + j;
            if (t >= no) {
                float* p = out + 3LL * Tc + 3LL * t;
                p[0] = -1.f; p[1] = -1.f; p[2] = -1.f;
            }
        }
    }
}

extern "C" void kernel_launch(void* const* d_in, const int* in_sizes, int n_in,
                              void* d_out, int out_size) {
    // Identify inputs by SIZE: coordinates = [B,N,3] (3*BNc), batch = [B,N] (BNc).
    const int* coords = (const int*)d_in[0];
    const int* batch  = (const int*)d_in[n_in > 1 ? 1 : 0];
    for (int i = 0; i < n_in; i++) {
        if (in_sizes[i] == 3 * BNc) coords = (const int*)d_in[i];
        else if (in_sizes[i] == BNc) batch = (const int*)d_in[i];
    }
    float* out = (float*)d_out;
    long long osz = (long long)out_size;

    long long tail = osz - (6LL * Tc + 1);
    if (tail > 0) k_tail<<<512, 256>>>(out + 6LL * Tc + 1, tail);

    k_build<<<(Tc + 255) / 256, 256>>>(coords, batch);
    k_bitset<<<(TABLE_SIZE / 4 + 255) / 256, 256>>>();
    k_scan<<<S1_BLOCKS, 256>>>(out);
    k_emit<<<(Tc + 255) / 256, 256>>>(out);
    k_out<<<(Tc / 8 + 255) / 256, 256>>>(out);
}